// round 6
// baseline (speedup 1.0000x reference)
#include <cuda_runtime.h>
#include <cuda_bf16.h>
#include <math.h>

// Static device scratch (zero-initialized at module load; counter is reset to 0
// by the last block every call, so every invocation is identical).
__device__ double       g_partials[8192];
__device__ unsigned int g_count = 0;

#define ROWS_PER_BLOCK 8
#define NTHREADS 256

__device__ __forceinline__ float fsqrt_approx(float x) {
    float y;
    asm("sqrt.approx.f32 %0, %1;" : "=f"(y) : "f"(x));
    return y;
}

__device__ __forceinline__ void euler_to_R(float a, float b, float c, float* R) {
    // R = Rx(a) @ Ry(b) @ Rz(c)
    float ca = cosf(a), sa = sinf(a);
    float cb = cosf(b), sb = sinf(b);
    float cc = cosf(c), sc = sinf(c);
    R[0] = cb * cc;                R[1] = -cb * sc;               R[2] = sb;
    R[3] = ca * sc + sa * sb * cc; R[4] = ca * cc - sa * sb * sc; R[5] = -sa * cb;
    R[6] = sa * sc - ca * sb * cc; R[7] = sa * cc + ca * sb * sc; R[8] = ca * cb;
}

__global__ __launch_bounds__(NTHREADS, 8)
void add_loss_kernel(const float* __restrict__ pred,
                     const float* __restrict__ mode,
                     const float* __restrict__ gt,
                     const float* __restrict__ point,
                     int N, int B, float* __restrict__ out, double inv_count)
{
    const int tid  = threadIdx.x;
    const int blk  = blockIdx.x;

    __shared__ float4 sparams[ROWS_PER_BLOCK];   // (ux, uy, uz, k) per row
    __shared__ double warp_sums[NTHREADS / 32];
    __shared__ int    s_is_last;

    // ---- per-row rotation params, 8 rows computed by 8 parallel threads ----
    if (tid < ROWS_PER_BLOCK) {
        const int row = blk * ROWS_PER_BLOCK + tid;

        // manifold2euler(pred, mode)
        float m1 = pred[row * 4 + 0];
        float m2 = pred[row * 4 + 1];
        float m3 = pred[row * 4 + 2];
        float m4 = pred[row * 4 + 3];
        float sgn   = (mode[row] > 0.5f) ? 1.0f : -1.0f;
        float denom = m1 * m1 + m2 * m2 + m3 * m3;
        float e2  = sgn * asinf(sqrtf((m3 * m3) / denom));
        float e3  = atan2f(m4, m3 / (sinf(e2) + 1e-9f));
        float tmp = cosf(e2) * cosf(e3);
        float e1  = atan2f(m2 / tmp, m1 / tmp);
        // (the reference's +2pi wrap on euler3 doesn't change cos/sin -> matrix unchanged)

        float Rp[9], Rg[9];
        euler_to_R(e1, e2, e3, Rp);
        euler_to_R(gt[row * 3 + 0], gt[row * 3 + 1], gt[row * 3 + 2], Rg);

        // M = Rp * Rg^T. Need trace + antisymmetric part only.
        // M[i][j] = sum_l Rp[i][l] * Rg[j][l]
        float M00 = Rp[0]*Rg[0] + Rp[1]*Rg[1] + Rp[2]*Rg[2];
        float M11 = Rp[3]*Rg[3] + Rp[4]*Rg[4] + Rp[5]*Rg[5];
        float M22 = Rp[6]*Rg[6] + Rp[7]*Rg[7] + Rp[8]*Rg[8];
        float M01 = Rp[0]*Rg[3] + Rp[1]*Rg[4] + Rp[2]*Rg[5];
        float M10 = Rp[3]*Rg[0] + Rp[4]*Rg[1] + Rp[5]*Rg[2];
        float M02 = Rp[0]*Rg[6] + Rp[1]*Rg[7] + Rp[2]*Rg[8];
        float M20 = Rp[6]*Rg[0] + Rp[7]*Rg[1] + Rp[8]*Rg[2];
        float M12 = Rp[3]*Rg[6] + Rp[4]*Rg[7] + Rp[5]*Rg[8];
        float M21 = Rp[6]*Rg[3] + Rp[7]*Rg[4] + Rp[8]*Rg[5];

        float tr = M00 + M11 + M22;
        // axis direction (unnormalized): 2*sin(theta)*u
        float w1 = M21 - M12, w2 = M02 - M20, w3 = M10 - M01;
        // ||p(M-I)|| = k * sqrt(||p||^2 - (p.u)^2), k = sqrt(3 - tr) = 2|sin(theta/2)|
        float k  = sqrtf(fmaxf(3.0f - tr, 0.0f));
        float wn2 = w1 * w1 + w2 * w2 + w3 * w3;
        float winv = rsqrtf(fmaxf(wn2, 1e-30f));
        sparams[tid] = make_float4(w1 * winv, w2 * winv, w3 * winv, k);
    }
    __syncthreads();

    // ---- streaming phase: 8 rows x N points, fully coalesced float4 loads ----
    // Hoist all per-row params and issue all 24 LDG.128 up front (high MLP),
    // then do the math. Rows are independent -> loads can all be in flight.
    const int ngroups = N >> 2;            // 4 points (48B) per group
    const size_t row_stride_f4 = (size_t)N * 3 / 4;

    float4 P[ROWS_PER_BLOCK];
    #pragma unroll
    for (int r = 0; r < ROWS_PER_BLOCK; r++) P[r] = sparams[r];

    const float4* pb0 = reinterpret_cast<const float4*>(
        point + (size_t)blk * ROWS_PER_BLOCK * N * 3);

    float sum = 0.0f;
    for (int g = tid; g < ngroups; g += NTHREADS) {
        float4 v[ROWS_PER_BLOCK][3];
        #pragma unroll
        for (int r = 0; r < ROWS_PER_BLOCK; r++) {
            const float4* pb = pb0 + (size_t)r * row_stride_f4 + 3 * g;
            v[r][0] = pb[0];
            v[r][1] = pb[1];
            v[r][2] = pb[2];
        }

        #pragma unroll
        for (int r = 0; r < ROWS_PER_BLOCK; r++) {
            const float ux = P[r].x, uy = P[r].y, uz = P[r].z, k = P[r].w;
            float x, y, z, n, d, w, srow = 0.0f;

            x = v[r][0].x; y = v[r][0].y; z = v[r][0].z;
            n = fmaf(x, x, fmaf(y, y, z * z));
            d = fmaf(x, ux, fmaf(y, uy, z * uz));
            w = fmaxf(fmaf(-d, d, n), 0.0f);
            srow += fsqrt_approx(w);

            x = v[r][0].w; y = v[r][1].x; z = v[r][1].y;
            n = fmaf(x, x, fmaf(y, y, z * z));
            d = fmaf(x, ux, fmaf(y, uy, z * uz));
            w = fmaxf(fmaf(-d, d, n), 0.0f);
            srow += fsqrt_approx(w);

            x = v[r][1].z; y = v[r][1].w; z = v[r][2].x;
            n = fmaf(x, x, fmaf(y, y, z * z));
            d = fmaf(x, ux, fmaf(y, uy, z * uz));
            w = fmaxf(fmaf(-d, d, n), 0.0f);
            srow += fsqrt_approx(w);

            x = v[r][2].y; y = v[r][2].z; z = v[r][2].w;
            n = fmaf(x, x, fmaf(y, y, z * z));
            d = fmaf(x, ux, fmaf(y, uy, z * uz));
            w = fmaxf(fmaf(-d, d, n), 0.0f);
            srow += fsqrt_approx(w);

            sum = fmaf(k, srow, sum);
        }
    }

    // ---- block reduce -> per-block partial (double) ----
    #pragma unroll
    for (int o = 16; o > 0; o >>= 1)
        sum += __shfl_xor_sync(0xFFFFFFFFu, sum, o);
    if ((tid & 31) == 0) warp_sums[tid >> 5] = (double)sum;
    __syncthreads();

    if (tid == 0) {
        double s = 0.0;
        #pragma unroll
        for (int i = 0; i < NTHREADS / 32; i++) s += warp_sums[i];
        g_partials[blk] = s;
        __threadfence();
        unsigned int old = atomicAdd(&g_count, 1u);
        s_is_last = (old == gridDim.x - 1) ? 1 : 0;
    }
    __syncthreads();

    // ---- last block finishes: reduce all partials, write output ----
    if (s_is_last) {
        __threadfence();
        const int nblocks = gridDim.x;
        double s = 0.0;
        for (int i = tid; i < nblocks; i += NTHREADS) s += g_partials[i];
        // reduce doubles across the block
        #pragma unroll
        for (int o = 16; o > 0; o >>= 1)
            s += __shfl_xor_sync(0xFFFFFFFFu, s, o);
        if ((tid & 31) == 0) warp_sums[tid >> 5] = s;
        __syncthreads();
        if (tid == 0) {
            double t = 0.0;
            #pragma unroll
            for (int i = 0; i < NTHREADS / 32; i++) t += warp_sums[i];
            out[0] = (float)(t * inv_count);
            g_count = 0;   // reset for next invocation (determinism)
        }
    }
}

extern "C" void kernel_launch(void* const* d_in, const int* in_sizes, int n_in,
                              void* d_out, int out_size) {
    const float* pred  = (const float*)d_in[0];   // (B, 4)
    const float* mode  = (const float*)d_in[1];   // (B,)
    const float* gt    = (const float*)d_in[2];   // (B, 3)
    const float* point = (const float*)d_in[3];   // (B, N, 3)

    const int B = in_sizes[1];
    const int N = in_sizes[3] / (B * 3);
    const int grid = B / ROWS_PER_BLOCK;

    add_loss_kernel<<<grid, NTHREADS>>>(pred, mode, gt, point, N, B,
                                        (float*)d_out,
                                        1.0 / ((double)B * (double)N));
}

// round 9
// speedup vs baseline: 1.5862x; 1.5862x over previous
#include <cuda_runtime.h>
#include <cuda_bf16.h>
#include <math.h>

// Static device scratch (zero-initialized at module load; counter is reset to 0
// by the last block every call, so every invocation is identical).
__device__ double       g_partials[8192];
__device__ unsigned int g_count = 0;

#define ROWS_PER_BLOCK 8
#define NTHREADS 256

__device__ __forceinline__ float fsqrt_approx(float x) {
    float y;
    asm("sqrt.approx.f32 %0, %1;" : "=f"(y) : "f"(x));
    return y;
}

__device__ __forceinline__ void euler_to_R(float a, float b, float c, float* R) {
    // R = Rx(a) @ Ry(b) @ Rz(c)
    float ca = cosf(a), sa = sinf(a);
    float cb = cosf(b), sb = sinf(b);
    float cc = cosf(c), sc = sinf(c);
    R[0] = cb * cc;                R[1] = -cb * sc;               R[2] = sb;
    R[3] = ca * sc + sa * sb * cc; R[4] = ca * cc - sa * sb * sc; R[5] = -sa * cb;
    R[6] = sa * sc - ca * sb * cc; R[7] = sa * cc + ca * sb * sc; R[8] = ca * cb;
}

// Compute k*sqrt(max(||p||^2 - (p.u)^2, 0)) for the 4 points packed in v0,v1,v2
// and accumulate into sum.
__device__ __forceinline__ void accum_group(float4 v0, float4 v1, float4 v2,
                                            float ux, float uy, float uz, float k,
                                            float& sum) {
    float x, y, z, n, d, w, srow = 0.0f;

    x = v0.x; y = v0.y; z = v0.z;
    n = fmaf(x, x, fmaf(y, y, z * z));
    d = fmaf(x, ux, fmaf(y, uy, z * uz));
    w = fmaxf(fmaf(-d, d, n), 0.0f);
    srow += fsqrt_approx(w);

    x = v0.w; y = v1.x; z = v1.y;
    n = fmaf(x, x, fmaf(y, y, z * z));
    d = fmaf(x, ux, fmaf(y, uy, z * uz));
    w = fmaxf(fmaf(-d, d, n), 0.0f);
    srow += fsqrt_approx(w);

    x = v1.z; y = v1.w; z = v2.x;
    n = fmaf(x, x, fmaf(y, y, z * z));
    d = fmaf(x, ux, fmaf(y, uy, z * uz));
    w = fmaxf(fmaf(-d, d, n), 0.0f);
    srow += fsqrt_approx(w);

    x = v2.y; y = v2.z; z = v2.w;
    n = fmaf(x, x, fmaf(y, y, z * z));
    d = fmaf(x, ux, fmaf(y, uy, z * uz));
    w = fmaxf(fmaf(-d, d, n), 0.0f);
    srow += fsqrt_approx(w);

    sum = fmaf(k, srow, sum);
}

__global__ __launch_bounds__(NTHREADS, 4)   // 64-reg budget: NO spills
void add_loss_kernel(const float* __restrict__ pred,
                     const float* __restrict__ mode,
                     const float* __restrict__ gt,
                     const float* __restrict__ point,
                     int N, int B, float* __restrict__ out, double inv_count)
{
    const int tid  = threadIdx.x;
    const int blk  = blockIdx.x;

    __shared__ float4 sparams[ROWS_PER_BLOCK];   // (ux, uy, uz, k) per row
    __shared__ double warp_sums[NTHREADS / 32];
    __shared__ int    s_is_last;

    // ---- per-row rotation params, 8 rows computed by 8 parallel threads ----
    if (tid < ROWS_PER_BLOCK) {
        const int row = blk * ROWS_PER_BLOCK + tid;

        // manifold2euler(pred, mode)
        float m1 = pred[row * 4 + 0];
        float m2 = pred[row * 4 + 1];
        float m3 = pred[row * 4 + 2];
        float m4 = pred[row * 4 + 3];
        float sgn   = (mode[row] > 0.5f) ? 1.0f : -1.0f;
        float denom = m1 * m1 + m2 * m2 + m3 * m3;
        float e2  = sgn * asinf(sqrtf((m3 * m3) / denom));
        float e3  = atan2f(m4, m3 / (sinf(e2) + 1e-9f));
        float tmp = cosf(e2) * cosf(e3);
        float e1  = atan2f(m2 / tmp, m1 / tmp);
        // (the reference's +2pi wrap on euler3 doesn't change cos/sin -> matrix unchanged)

        float Rp[9], Rg[9];
        euler_to_R(e1, e2, e3, Rp);
        euler_to_R(gt[row * 3 + 0], gt[row * 3 + 1], gt[row * 3 + 2], Rg);

        // M = Rp * Rg^T; need trace + antisymmetric part only.
        float M00 = Rp[0]*Rg[0] + Rp[1]*Rg[1] + Rp[2]*Rg[2];
        float M11 = Rp[3]*Rg[3] + Rp[4]*Rg[4] + Rp[5]*Rg[5];
        float M22 = Rp[6]*Rg[6] + Rp[7]*Rg[7] + Rp[8]*Rg[8];
        float M01 = Rp[0]*Rg[3] + Rp[1]*Rg[4] + Rp[2]*Rg[5];
        float M10 = Rp[3]*Rg[0] + Rp[4]*Rg[1] + Rp[5]*Rg[2];
        float M02 = Rp[0]*Rg[6] + Rp[1]*Rg[7] + Rp[2]*Rg[8];
        float M20 = Rp[6]*Rg[0] + Rp[7]*Rg[1] + Rp[8]*Rg[2];
        float M12 = Rp[3]*Rg[6] + Rp[4]*Rg[7] + Rp[5]*Rg[8];
        float M21 = Rp[6]*Rg[3] + Rp[7]*Rg[4] + Rp[8]*Rg[5];

        float tr = M00 + M11 + M22;
        float w1 = M21 - M12, w2 = M02 - M20, w3 = M10 - M01;
        // ||p(M-I)|| = k * sqrt(||p||^2 - (p.u)^2), k = sqrt(3 - tr) = 2|sin(theta/2)|
        float k  = sqrtf(fmaxf(3.0f - tr, 0.0f));
        float wn2 = w1 * w1 + w2 * w2 + w3 * w3;
        float winv = rsqrtf(fmaxf(wn2, 1e-30f));
        sparams[tid] = make_float4(w1 * winv, w2 * winv, w3 * winv, k);
    }
    __syncthreads();

    // ---- streaming: rows processed in PAIRS -> 6 independent LDG.128/thread ----
    // N=1024 -> ngroups=256 == NTHREADS: each thread does exactly one 48B group
    // per row. Pairing keeps register use ~48 (no spill at 64-reg budget).
    const int ngroups = N >> 2;
    const size_t row_stride_f4 = (size_t)N * 3 / 4;
    const float4* pb0 = reinterpret_cast<const float4*>(
        point + (size_t)blk * ROWS_PER_BLOCK * N * 3);

    float sum = 0.0f;

    for (int g = tid; g < ngroups; g += NTHREADS) {
        #pragma unroll
        for (int rp = 0; rp < ROWS_PER_BLOCK / 2; rp++) {
            const int r0 = 2 * rp, r1 = 2 * rp + 1;
            const float4* a = pb0 + (size_t)r0 * row_stride_f4 + 3 * g;
            const float4* b = pb0 + (size_t)r1 * row_stride_f4 + 3 * g;

            // 6 independent 128-bit loads in flight
            float4 a0 = a[0], a1 = a[1], a2 = a[2];
            float4 b0 = b[0], b1 = b[1], b2 = b[2];

            float4 Pa = sparams[r0];
            float4 Pb = sparams[r1];

            accum_group(a0, a1, a2, Pa.x, Pa.y, Pa.z, Pa.w, sum);
            accum_group(b0, b1, b2, Pb.x, Pb.y, Pb.z, Pb.w, sum);
        }
    }

    // ---- block reduce -> per-block partial (double) ----
    #pragma unroll
    for (int o = 16; o > 0; o >>= 1)
        sum += __shfl_xor_sync(0xFFFFFFFFu, sum, o);
    if ((tid & 31) == 0) warp_sums[tid >> 5] = (double)sum;
    __syncthreads();

    if (tid == 0) {
        double s = 0.0;
        #pragma unroll
        for (int i = 0; i < NTHREADS / 32; i++) s += warp_sums[i];
        g_partials[blk] = s;
        __threadfence();
        unsigned int old = atomicAdd(&g_count, 1u);
        s_is_last = (old == gridDim.x - 1) ? 1 : 0;
    }
    __syncthreads();

    // ---- last block finishes: reduce all partials, write output ----
    if (s_is_last) {
        __threadfence();
        const int nblocks = gridDim.x;
        double s = 0.0;
        for (int i = tid; i < nblocks; i += NTHREADS) s += g_partials[i];
        #pragma unroll
        for (int o = 16; o > 0; o >>= 1)
            s += __shfl_xor_sync(0xFFFFFFFFu, s, o);
        if ((tid & 31) == 0) warp_sums[tid >> 5] = s;
        __syncthreads();
        if (tid == 0) {
            double t = 0.0;
            #pragma unroll
            for (int i = 0; i < NTHREADS / 32; i++) t += warp_sums[i];
            out[0] = (float)(t * inv_count);
            g_count = 0;   // reset for next invocation (determinism)
        }
    }
}

extern "C" void kernel_launch(void* const* d_in, const int* in_sizes, int n_in,
                              void* d_out, int out_size) {
    const float* pred  = (const float*)d_in[0];   // (B, 4)
    const float* mode  = (const float*)d_in[1];   // (B,)
    const float* gt    = (const float*)d_in[2];   // (B, 3)
    const float* point = (const float*)d_in[3];   // (B, N, 3)

    const int B = in_sizes[1];
    const int N = in_sizes[3] / (B * 3);
    const int grid = B / ROWS_PER_BLOCK;

    add_loss_kernel<<<grid, NTHREADS>>>(pred, mode, gt, point, N, B,
                                        (float*)d_out,
                                        1.0 / ((double)B * (double)N));
}

// round 10
// speedup vs baseline: 1.9918x; 1.2557x over previous
#include <cuda_runtime.h>
#include <cuda_bf16.h>
#include <math.h>

// Static device scratch (no allocation allowed).
__device__ float4       g_params[8192];    // (ux, uy, uz, k) per batch row
__device__ double       g_partials[8192];
__device__ unsigned int g_count = 0;

#define NTHREADS   256
#define CTAS_PER_SM 4
#define NUM_SMS     152      // GB300; harmless if actual count differs slightly

__device__ __forceinline__ float fsqrt_approx(float x) {
    float y;
    asm("sqrt.approx.f32 %0, %1;" : "=f"(y) : "f"(x));
    return y;
}

__device__ __forceinline__ void euler_to_R(float a, float b, float c, float* R) {
    // R = Rx(a) @ Ry(b) @ Rz(c)
    float ca = cosf(a), sa = sinf(a);
    float cb = cosf(b), sb = sinf(b);
    float cc = cosf(c), sc = sinf(c);
    R[0] = cb * cc;                R[1] = -cb * sc;               R[2] = sb;
    R[3] = ca * sc + sa * sb * cc; R[4] = ca * cc - sa * sb * sc; R[5] = -sa * cb;
    R[6] = sa * sc - ca * sb * cc; R[7] = sa * cc + ca * sb * sc; R[8] = ca * cb;
}

// ---------------- Kernel 1: per-row rotation params ----------------
__global__ void params_kernel(const float* __restrict__ pred,
                              const float* __restrict__ mode,
                              const float* __restrict__ gt,
                              int B)
{
    const int row = blockIdx.x * blockDim.x + threadIdx.x;
    if (row >= B) return;

    float m1 = pred[row * 4 + 0];
    float m2 = pred[row * 4 + 1];
    float m3 = pred[row * 4 + 2];
    float m4 = pred[row * 4 + 3];
    float sgn   = (mode[row] > 0.5f) ? 1.0f : -1.0f;
    float denom = m1 * m1 + m2 * m2 + m3 * m3;
    float e2  = sgn * asinf(sqrtf((m3 * m3) / denom));
    float e3  = atan2f(m4, m3 / (sinf(e2) + 1e-9f));
    float tmp = cosf(e2) * cosf(e3);
    float e1  = atan2f(m2 / tmp, m1 / tmp);
    // (+2pi wrap on euler3 doesn't change cos/sin -> matrix unchanged)

    float Rp[9], Rg[9];
    euler_to_R(e1, e2, e3, Rp);
    euler_to_R(gt[row * 3 + 0], gt[row * 3 + 1], gt[row * 3 + 2], Rg);

    // M = Rp * Rg^T; need trace + antisymmetric part only.
    float M00 = Rp[0]*Rg[0] + Rp[1]*Rg[1] + Rp[2]*Rg[2];
    float M11 = Rp[3]*Rg[3] + Rp[4]*Rg[4] + Rp[5]*Rg[5];
    float M22 = Rp[6]*Rg[6] + Rp[7]*Rg[7] + Rp[8]*Rg[8];
    float M01 = Rp[0]*Rg[3] + Rp[1]*Rg[4] + Rp[2]*Rg[5];
    float M10 = Rp[3]*Rg[0] + Rp[4]*Rg[1] + Rp[5]*Rg[2];
    float M02 = Rp[0]*Rg[6] + Rp[1]*Rg[7] + Rp[2]*Rg[8];
    float M20 = Rp[6]*Rg[0] + Rp[7]*Rg[1] + Rp[8]*Rg[2];
    float M12 = Rp[3]*Rg[6] + Rp[4]*Rg[7] + Rp[5]*Rg[8];
    float M21 = Rp[6]*Rg[3] + Rp[7]*Rg[4] + Rp[8]*Rg[5];

    float tr = M00 + M11 + M22;
    float w1 = M21 - M12, w2 = M02 - M20, w3 = M10 - M01;
    // ||p(M-I)|| = k*sqrt(||p||^2 - (p.u)^2), k = sqrt(3-tr) = 2|sin(theta/2)|
    float k    = sqrtf(fmaxf(3.0f - tr, 0.0f));
    float wn2  = w1 * w1 + w2 * w2 + w3 * w3;
    float winv = rsqrtf(fmaxf(wn2, 1e-30f));
    g_params[row] = make_float4(w1 * winv, w2 * winv, w3 * winv, k);
}

// One group = 4 points = 3 float4, all in the same row.
__device__ __forceinline__ float group_sum(float4 v0, float4 v1, float4 v2,
                                           float4 P) {
    const float ux = P.x, uy = P.y, uz = P.z;
    float x, y, z, n, d, w, s = 0.0f;

    x = v0.x; y = v0.y; z = v0.z;
    n = fmaf(x, x, fmaf(y, y, z * z));
    d = fmaf(x, ux, fmaf(y, uy, z * uz));
    w = fmaxf(fmaf(-d, d, n), 0.0f);
    s += fsqrt_approx(w);

    x = v0.w; y = v1.x; z = v1.y;
    n = fmaf(x, x, fmaf(y, y, z * z));
    d = fmaf(x, ux, fmaf(y, uy, z * uz));
    w = fmaxf(fmaf(-d, d, n), 0.0f);
    s += fsqrt_approx(w);

    x = v1.z; y = v1.w; z = v2.x;
    n = fmaf(x, x, fmaf(y, y, z * z));
    d = fmaf(x, ux, fmaf(y, uy, z * uz));
    w = fmaxf(fmaf(-d, d, n), 0.0f);
    s += fsqrt_approx(w);

    x = v2.y; y = v2.z; z = v2.w;
    n = fmaf(x, x, fmaf(y, y, z * z));
    d = fmaf(x, ux, fmaf(y, uy, z * uz));
    w = fmaxf(fmaf(-d, d, n), 0.0f);
    s += fsqrt_approx(w);

    return P.w * s;   // scale by k
}

// ---------------- Kernel 2: persistent flat streamer ----------------
__global__ __launch_bounds__(NTHREADS, CTAS_PER_SM)
void stream_kernel(const float* __restrict__ point,
                   int ngroups,          // B*N/4 total groups
                   int gpr_shift,        // log2(N/4): groups per row
                   float* __restrict__ out, double inv_count)
{
    const int tid    = threadIdx.x;
    const int total  = gridDim.x * NTHREADS;
    const float4* pf = reinterpret_cast<const float4*>(point);

    __shared__ double warp_sums[NTHREADS / 32];
    __shared__ int    s_is_last;

    float sum = 0.0f;

    // 2 groups per iteration -> 6 independent LDG.128 + 2 L1-hot param loads.
    for (int g0 = blockIdx.x * NTHREADS + tid; g0 < ngroups; g0 += 2 * total) {
        const int g1 = g0 + total;
        const bool do1 = (g1 < ngroups);

        const float4* a = pf + 3 * (size_t)g0;
        float4 a0 = a[0], a1 = a[1], a2 = a[2];

        float4 b0, b1, b2;
        if (do1) {
            const float4* b = pf + 3 * (size_t)g1;
            b0 = b[0]; b1 = b[1]; b2 = b[2];
        }

        float4 Pa = __ldg(&g_params[g0 >> gpr_shift]);
        sum += group_sum(a0, a1, a2, Pa);

        if (do1) {
            float4 Pb = __ldg(&g_params[g1 >> gpr_shift]);
            sum += group_sum(b0, b1, b2, Pb);
        }
    }

    // ---- block reduce -> per-block partial (double) ----
    #pragma unroll
    for (int o = 16; o > 0; o >>= 1)
        sum += __shfl_xor_sync(0xFFFFFFFFu, sum, o);
    if ((tid & 31) == 0) warp_sums[tid >> 5] = (double)sum;
    __syncthreads();

    if (tid == 0) {
        double s = 0.0;
        #pragma unroll
        for (int i = 0; i < NTHREADS / 32; i++) s += warp_sums[i];
        g_partials[blockIdx.x] = s;
        __threadfence();
        unsigned int old = atomicAdd(&g_count, 1u);
        s_is_last = (old == gridDim.x - 1) ? 1 : 0;
    }
    __syncthreads();

    if (s_is_last) {
        __threadfence();
        const int nblocks = gridDim.x;
        double s = 0.0;
        for (int i = tid; i < nblocks; i += NTHREADS) s += g_partials[i];
        #pragma unroll
        for (int o = 16; o > 0; o >>= 1)
            s += __shfl_xor_sync(0xFFFFFFFFu, s, o);
        if ((tid & 31) == 0) warp_sums[tid >> 5] = s;
        __syncthreads();
        if (tid == 0) {
            double t = 0.0;
            #pragma unroll
            for (int i = 0; i < NTHREADS / 32; i++) t += warp_sums[i];
            out[0] = (float)(t * inv_count);
            g_count = 0;   // reset for next invocation (determinism)
        }
    }
}

extern "C" void kernel_launch(void* const* d_in, const int* in_sizes, int n_in,
                              void* d_out, int out_size) {
    const float* pred  = (const float*)d_in[0];   // (B, 4)
    const float* mode  = (const float*)d_in[1];   // (B,)
    const float* gt    = (const float*)d_in[2];   // (B, 3)
    const float* point = (const float*)d_in[3];   // (B, N, 3)

    const int B = in_sizes[1];
    const int N = in_sizes[3] / (B * 3);

    const int ngroups = (B * N) >> 2;      // 4 points per group
    const int gpr     = N >> 2;            // groups per row (power of 2 here)
    int gpr_shift = 0;
    while ((1 << gpr_shift) < gpr) gpr_shift++;

    params_kernel<<<(B + NTHREADS - 1) / NTHREADS, NTHREADS>>>(pred, mode, gt, B);

    const int grid = NUM_SMS * CTAS_PER_SM;   // exactly one wave at occ 4
    stream_kernel<<<grid, NTHREADS>>>(point, ngroups, gpr_shift,
                                      (float*)d_out,
                                      1.0 / ((double)B * (double)N));
}